// round 3
// baseline (speedup 1.0000x reference)
#include <cuda_runtime.h>
#include <stdint.h>

#define NSITES   144
#define NHID     256
#define G3       768
#define BATCH    1024
#define NB       8
#define NBLOCKS  (BATCH / NB)
#define SSTRIDE  10          // h_s row stride (floats): 8-byte aligned rows, conflict-friendly

// ---------------- threefry2x32 core (JAX schedule) ----------------
__device__ __forceinline__ uint32_t rotl32(uint32_t x, uint32_t r) {
    return __funnelshift_l(x, x, r);
}

__device__ __forceinline__ void tf2x32(uint32_t k0, uint32_t k1,
                                       uint32_t x0, uint32_t x1,
                                       uint32_t &o0, uint32_t &o1) {
    uint32_t k2 = k0 ^ k1 ^ 0x1BD11BDAu;
    x0 += k0; x1 += k1;
#define TFR(r) { x0 += x1; x1 = rotl32(x1, r); x1 ^= x0; }
    TFR(13) TFR(15) TFR(26) TFR(6)    x0 += k1; x1 += k2 + 1u;
    TFR(17) TFR(29) TFR(16) TFR(24)   x0 += k2; x1 += k0 + 2u;
    TFR(13) TFR(15) TFR(26) TFR(6)    x0 += k0; x1 += k1 + 3u;
    TFR(17) TFR(29) TFR(16) TFR(24)   x0 += k1; x1 += k2 + 4u;
    TFR(13) TFR(15) TFR(26) TFR(6)    x0 += k2; x1 += k0 + 5u;
#undef TFR
    o0 = x0; o1 = x1;
}

// Partitionable random_bits (32-bit): element at flat index i is
// w0 ^ w1 of threefry2x32(key, (hi32(i)=0, lo32(i)=i)).
__device__ __forceinline__ uint32_t rbits_part(uint32_t k0, uint32_t k1, uint32_t i) {
    uint32_t o0, o1;
    tf2x32(k0, k1, 0u, i, o0, o1);
    return o0 ^ o1;
}

// jax.random.gumbel: -log(-log(uniform(tiny, 1)))
__device__ __forceinline__ float gumbel_from(uint32_t bits) {
    const float TINY = 1.17549435e-38f;
    float f = __uint_as_float((bits >> 9) | 0x3f800000u) - 1.0f;
    float u = fmaxf(TINY, f + TINY);     // f*(1-tiny)+tiny == f+tiny in fp32
    return -logf(-logf(u));
}

// ---------------- packed f32x2 FMA (sm_100+) ----------------
__device__ __forceinline__ unsigned long long pack2(float x) {
    unsigned long long r;
    asm("mov.b64 %0, {%1, %1};" : "=l"(r) : "f"(x));
    return r;
}
__device__ __forceinline__ void fma2(unsigned long long &d, unsigned long long a,
                                     unsigned long long b) {
    asm("fma.rn.f32x2 %0, %1, %2, %0;" : "+l"(d) : "l"(a), "l"(b));
}
__device__ __forceinline__ void unpack2(unsigned long long v, float &lo, float &hi) {
    asm("mov.b64 {%0, %1}, %2;" : "=f"(lo), "=f"(hi) : "l"(v));
}

__device__ __forceinline__ float sigmoid_x(float x) {
    return 0.5f + 0.5f * tanhf(0.5f * x);
}

__global__ void __launch_bounds__(256, 1)
rnn_sample_kernel(const float* __restrict__ Wx,    // kernel      [2, 768]
                  const float* __restrict__ Wh,    // rec_kernel  [256, 768]
                  const float* __restrict__ bias,  // [2, 768]
                  const float* __restrict__ Dw,    // dense_w     [256, 2]
                  const float* __restrict__ Db,    // dense_b     [2]
                  float* __restrict__ out)         // samples [1024,144] then logP [1024]
{
    __shared__ __align__(16) float h_s[NHID * SSTRIDE];  // layout [k][b]
    __shared__ int s_arr[NB];
    __shared__ uint32_t kt_s[NSITES][2];                 // per-step keys

    const int tid  = threadIdx.x;
    const int lane = tid & 31;
    const int warp = tid >> 5;
    const int bbase = blockIdx.x * NB;

    for (int i = tid; i < NHID * SSTRIDE; i += 256) h_s[i] = 0.0f;
    if (tid < NB) s_arr[tid] = -1;
    // Partitionable split: key_t = full output pair of tf2x32(key(0,42), (0, t))
    if (tid < NSITES) {
        uint32_t o0, o1;
        tf2x32(0u, 42u, 0u, (uint32_t)tid, o0, o1);
        kt_s[tid][0] = o0; kt_s[tid][1] = o1;
    }
    float logP = 0.0f;   // owned by lane 0 of each warp (sample = warp id)
    __syncthreads();

    const int j = tid;   // gate unit / output column
    const float b0z = bias[j],       b0r = bias[256 + j],  b0n = bias[512 + j];
    const float b1z = bias[768 + j], b1r = bias[1024 + j], b1n = bias[1280 + j];
    const float db0 = Db[0], db1 = Db[1];

    for (int t = 0; t < NSITES; ++t) {
        // ---------- gh = h @ Wh : columns j, j+256, j+512 for 8 samples ----------
        unsigned long long acc[12];
#pragma unroll
        for (int i = 0; i < 12; ++i) acc[i] = 0ull;
        const float* wp = Wh + j;
#pragma unroll 4
        for (int k = 0; k < NHID; ++k) {
            unsigned long long w0 = pack2(wp[0]);
            unsigned long long w1 = pack2(wp[256]);
            unsigned long long w2 = pack2(wp[512]);
            wp += G3;
            const unsigned long long* hp =
                reinterpret_cast<const unsigned long long*>(h_s + k * SSTRIDE);
            unsigned long long h01 = hp[0], h23 = hp[1], h45 = hp[2], h67 = hp[3];
            fma2(acc[0], w0, h01); fma2(acc[1], w0, h23);
            fma2(acc[2], w0, h45); fma2(acc[3], w0, h67);
            fma2(acc[4], w1, h01); fma2(acc[5], w1, h23);
            fma2(acc[6], w1, h45); fma2(acc[7], w1, h67);
            fma2(acc[8], w2, h01); fma2(acc[9], w2, h23);
            fma2(acc[10], w2, h45); fma2(acc[11], w2, h67);
        }

        float ghz[NB], ghr[NB], ghn[NB];
#pragma unroll
        for (int p = 0; p < 4; ++p) {
            unpack2(acc[p],     ghz[2 * p], ghz[2 * p + 1]);
            unpack2(acc[4 + p], ghr[2 * p], ghr[2 * p + 1]);
            unpack2(acc[8 + p], ghn[2 * p], ghn[2 * p + 1]);
        }

        // ---------- GRU gate math for unit j, all 8 samples ----------
        float hnew[NB];
#pragma unroll
        for (int b = 0; b < NB; ++b) {
            int sp = s_arr[b];
            float gxz = b0z, gxr = b0r, gxn = b0n;
            if (sp >= 0) {
                const float* kr = Wx + sp * G3;
                gxz = kr[j] + b0z;
                gxr = kr[256 + j] + b0r;
                gxn = kr[512 + j] + b0n;
            }
            float hz = ghz[b] + b1z;
            float hr = ghr[b] + b1r;
            float hn = ghn[b] + b1n;
            float z = sigmoid_x(gxz + hz);
            float r = sigmoid_x(gxr + hr);
            float hh = tanhf(gxn + r * hn);
            float hold = h_s[j * SSTRIDE + b];
            hnew[b] = z * hold + (1.0f - z) * hh;
        }
        __syncthreads();   // all reads of old h complete
#pragma unroll
        for (int b = 0; b < NB; ++b) h_s[j * SSTRIDE + b] = hnew[b];
        __syncthreads();

        // ---------- dense head + softmax + categorical (warp w -> sample w) ----------
        {
            const int b = warp;
            float c0 = 0.0f, c1 = 0.0f;
            for (int k = lane; k < NHID; k += 32) {
                float hv = h_s[k * SSTRIDE + b];
                c0 += hv * Dw[2 * k];
                c1 += hv * Dw[2 * k + 1];
            }
#pragma unroll
            for (int off = 16; off > 0; off >>= 1) {
                c0 += __shfl_down_sync(0xffffffffu, c0, off);
                c1 += __shfl_down_sync(0xffffffffu, c1, off);
            }
            if (lane == 0) {
                float la = c0 + db0, lb = c1 + db1;
                float m  = fmaxf(la, lb);
                float ea = expf(la - m), eb = expf(lb - m);
                float sm = ea + eb;
                float lp0 = logf(1e-10f + ea / sm);
                float lp1 = logf(1e-10f + eb / sm);
                uint32_t kt0 = kt_s[t][0], kt1 = kt_s[t][1];
                int bg = bbase + b;
                // partitionable bits: flat index i = 2*bg + class
                float g0 = gumbel_from(rbits_part(kt0, kt1, (uint32_t)(2 * bg)));
                float g1 = gumbel_from(rbits_part(kt0, kt1, (uint32_t)(2 * bg + 1)));
                int s = (g1 + lp1 > g0 + lp0) ? 1 : 0;   // argmax ties -> index 0
                logP += s ? lp1 : lp0;
                s_arr[b] = s;
                out[bg * NSITES + t] = (float)s;
            }
        }
        __syncthreads();
    }

    if (lane == 0) {
        out[BATCH * NSITES + bbase + warp] = logP;
    }
}

extern "C" void kernel_launch(void* const* d_in, const int* in_sizes, int n_in,
                              void* d_out, int out_size) {
    (void)in_sizes; (void)n_in; (void)out_size;
    const float* Wx   = (const float*)d_in[0];
    const float* Wh   = (const float*)d_in[1];
    const float* bias = (const float*)d_in[2];
    const float* Dw   = (const float*)d_in[3];
    const float* Db   = (const float*)d_in[4];
    float* out = (float*)d_out;
    rnn_sample_kernel<<<NBLOCKS, 256>>>(Wx, Wh, bias, Dw, Db, out);
}

// round 5
// speedup vs baseline: 1.5701x; 1.5701x over previous
#include <cuda_runtime.h>
#include <stdint.h>

#define NSITES   144
#define NHID     256
#define G3       768
#define BATCH    1024
#define NB       8
#define NBLOCKS  (BATCH / NB)
#define THREADS  512
#define KHALF    128
#define SSTRIDE  12          // h_s row stride (floats): 48B rows -> LDS.128-aligned

// ---------------- threefry2x32 core (JAX schedule) ----------------
__device__ __forceinline__ uint32_t rotl32(uint32_t x, uint32_t r) {
    return __funnelshift_l(x, x, r);
}

__device__ __forceinline__ void tf2x32(uint32_t k0, uint32_t k1,
                                       uint32_t x0, uint32_t x1,
                                       uint32_t &o0, uint32_t &o1) {
    uint32_t k2 = k0 ^ k1 ^ 0x1BD11BDAu;
    x0 += k0; x1 += k1;
#define TFR(r) { x0 += x1; x1 = rotl32(x1, r); x1 ^= x0; }
    TFR(13) TFR(15) TFR(26) TFR(6)    x0 += k1; x1 += k2 + 1u;
    TFR(17) TFR(29) TFR(16) TFR(24)   x0 += k2; x1 += k0 + 2u;
    TFR(13) TFR(15) TFR(26) TFR(6)    x0 += k0; x1 += k1 + 3u;
    TFR(17) TFR(29) TFR(16) TFR(24)   x0 += k1; x1 += k2 + 4u;
    TFR(13) TFR(15) TFR(26) TFR(6)    x0 += k2; x1 += k0 + 5u;
#undef TFR
    o0 = x0; o1 = x1;
}

// Partitionable random_bits (32-bit): element i = w0 ^ w1 of tf2x32(key, (0, i))
__device__ __forceinline__ uint32_t rbits_part(uint32_t k0, uint32_t k1, uint32_t i) {
    uint32_t o0, o1;
    tf2x32(k0, k1, 0u, i, o0, o1);
    return o0 ^ o1;
}

// jax.random.gumbel: -log(-log(uniform(tiny, 1)))
__device__ __forceinline__ float gumbel_from(uint32_t bits) {
    const float TINY = 1.17549435e-38f;
    float f = __uint_as_float((bits >> 9) | 0x3f800000u) - 1.0f;
    float u = fmaxf(TINY, f + TINY);
    return -logf(-logf(u));
}

// ---------------- packed f32x2 ops (sm_100+) ----------------
__device__ __forceinline__ unsigned long long pack2(float x) {
    unsigned long long r;
    asm("mov.b64 %0, {%1, %1};" : "=l"(r) : "f"(x));
    return r;
}
__device__ __forceinline__ void fma2(unsigned long long &d, unsigned long long a,
                                     unsigned long long b) {
    asm("fma.rn.f32x2 %0, %1, %2, %0;" : "+l"(d) : "l"(a), "l"(b));
}
__device__ __forceinline__ unsigned long long add2(unsigned long long a,
                                                   unsigned long long b) {
    unsigned long long r;
    asm("add.rn.f32x2 %0, %1, %2;" : "=l"(r) : "l"(a), "l"(b));
    return r;
}
__device__ __forceinline__ void unpack2(unsigned long long v, float &lo, float &hi) {
    asm("mov.b64 {%0, %1}, %2;" : "=f"(lo), "=f"(hi) : "l"(v));
}

__device__ __forceinline__ float sigmoid_x(float x) {
    return 0.5f + 0.5f * tanhf(0.5f * x);
}

__global__ void __launch_bounds__(THREADS, 1)
rnn_sample_kernel(const float* __restrict__ Wx,    // kernel      [2, 768]
                  const float* __restrict__ Wh,    // rec_kernel  [256, 768]
                  const float* __restrict__ bias,  // [2, 768]
                  const float* __restrict__ Dw,    // dense_w     [256, 2]
                  const float* __restrict__ Db,    // dense_b     [2]
                  float* __restrict__ out)         // samples [1024,144] then logP [1024]
{
    __shared__ __align__(16) float h_s[NHID * SSTRIDE];          // [k][b], 12KB
    __shared__ __align__(16) unsigned long long red_s[NHID][12]; // 24KB partials
    __shared__ float gx_s[3 * G3];                               // 9KB: [x-case][col]
    __shared__ uint32_t kt_s[NSITES][2];
    __shared__ int s_arr[NB];

    const int tid  = threadIdx.x;
    const int lane = tid & 31;
    const int warp = tid >> 5;
    const int half = tid >> 8;       // 0: k in [0,128), 1: k in [128,256)
    const int j    = tid & 255;      // gate unit
    const int bbase = blockIdx.x * NB;

    for (int i = tid; i < NHID * SSTRIDE; i += THREADS) h_s[i] = 0.0f;
    // gx LUT: case 0 = x=0 (t=0): bias only; case 1+s = one_hot(s): Wx[s]+bias
    for (int c = tid; c < G3; c += THREADS) {
        float b0 = bias[c];
        gx_s[c]           = b0;
        gx_s[G3 + c]      = Wx[c] + b0;
        gx_s[2 * G3 + c]  = Wx[G3 + c] + b0;
    }
    if (tid < NB) s_arr[tid] = -1;
    if (tid < NSITES) {
        uint32_t o0, o1;
        tf2x32(0u, 42u, 0u, (uint32_t)tid, o0, o1);
        kt_s[tid][0] = o0; kt_s[tid][1] = o1;
    }
    float logP = 0.0f;   // lane 0 of warps 0..7 (sample = warp id)
    __syncthreads();

    // recurrent bias (only lower half needs it for gate math)
    const float b1z = bias[G3 + j], b1r = bias[G3 + 256 + j], b1n = bias[G3 + 512 + j];
    const float db0 = Db[0], db1 = Db[1];
    const int k0 = half * KHALF;

    for (int t = 0; t < NSITES; ++t) {
        // ---------- partial gh = h @ Wh over this thread's k-half ----------
        unsigned long long acc[12];
#pragma unroll
        for (int i = 0; i < 12; ++i) acc[i] = 0ull;
        const float* wp = Wh + k0 * G3 + j;
#pragma unroll 4
        for (int k = k0; k < k0 + KHALF; ++k) {
            unsigned long long w0 = pack2(wp[0]);
            unsigned long long w1 = pack2(wp[256]);
            unsigned long long w2 = pack2(wp[512]);
            wp += G3;
            const ulonglong2* hp =
                reinterpret_cast<const ulonglong2*>(h_s + k * SSTRIDE);
            ulonglong2 hA = hp[0], hB = hp[1];
            fma2(acc[0], w0, hA.x); fma2(acc[1], w0, hA.y);
            fma2(acc[2], w0, hB.x); fma2(acc[3], w0, hB.y);
            fma2(acc[4], w1, hA.x); fma2(acc[5], w1, hA.y);
            fma2(acc[6], w1, hB.x); fma2(acc[7], w1, hB.y);
            fma2(acc[8], w2, hA.x); fma2(acc[9], w2, hA.y);
            fma2(acc[10], w2, hB.x); fma2(acc[11], w2, hB.y);
        }

        if (half == 1) {
#pragma unroll
            for (int i = 0; i < 12; ++i) red_s[j][i] = acc[i];
        }
        __syncthreads();

        // ---------- lower half: combine + GRU gate math ----------
        if (half == 0) {
#pragma unroll
            for (int i = 0; i < 12; ++i) acc[i] = add2(acc[i], red_s[j][i]);

            float ghz[NB], ghr[NB], ghn[NB];
#pragma unroll
            for (int p = 0; p < 4; ++p) {
                unpack2(acc[p],     ghz[2 * p], ghz[2 * p + 1]);
                unpack2(acc[4 + p], ghr[2 * p], ghr[2 * p + 1]);
                unpack2(acc[8 + p], ghn[2 * p], ghn[2 * p + 1]);
            }
            float hnew[NB];
#pragma unroll
            for (int b = 0; b < NB; ++b) {
                int idx = s_arr[b] + 1;                 // -1 -> 0 (x = 0 at t=0)
                float gxz = gx_s[idx * G3 + j];
                float gxr = gx_s[idx * G3 + 256 + j];
                float gxn = gx_s[idx * G3 + 512 + j];
                float z = sigmoid_x(gxz + ghz[b] + b1z);
                float r = sigmoid_x(gxr + ghr[b] + b1r);
                float hh = tanhf(gxn + r * (ghn[b] + b1n));
                float hold = h_s[j * SSTRIDE + b];
                hnew[b] = z * hold + (1.0f - z) * hh;
            }
#pragma unroll
            for (int b = 0; b < NB; ++b) h_s[j * SSTRIDE + b] = hnew[b];
        }
        __syncthreads();

        // ---------- dense head + softmax + categorical (warp w -> sample w) ----------
        if (warp < NB) {
            const int b = warp;
            float c0 = 0.0f, c1 = 0.0f;
            for (int k = lane; k < NHID; k += 32) {
                float hv = h_s[k * SSTRIDE + b];
                c0 += hv * Dw[2 * k];
                c1 += hv * Dw[2 * k + 1];
            }
#pragma unroll
            for (int off = 16; off > 0; off >>= 1) {
                c0 += __shfl_down_sync(0xffffffffu, c0, off);
                c1 += __shfl_down_sync(0xffffffffu, c1, off);
            }
            if (lane == 0) {
                float la = c0 + db0, lb = c1 + db1;
                float m  = fmaxf(la, lb);
                float ea = expf(la - m), eb = expf(lb - m);
                float sm = ea + eb;
                float lp0 = logf(1e-10f + ea / sm);
                float lp1 = logf(1e-10f + eb / sm);
                uint32_t kt0 = kt_s[t][0], kt1 = kt_s[t][1];
                int bg = bbase + b;
                float g0 = gumbel_from(rbits_part(kt0, kt1, (uint32_t)(2 * bg)));
                float g1 = gumbel_from(rbits_part(kt0, kt1, (uint32_t)(2 * bg + 1)));
                int s = (g1 + lp1 > g0 + lp0) ? 1 : 0;   // argmax ties -> index 0
                logP += s ? lp1 : lp0;
                s_arr[b] = s;
                out[bg * NSITES + t] = (float)s;
            }
        }
        __syncthreads();
    }

    if (warp < NB && lane == 0) {
        out[BATCH * NSITES + bbase + warp] = logP;
    }
}

extern "C" void kernel_launch(void* const* d_in, const int* in_sizes, int n_in,
                              void* d_out, int out_size) {
    (void)in_sizes; (void)n_in; (void)out_size;
    const float* Wx   = (const float*)d_in[0];
    const float* Wh   = (const float*)d_in[1];
    const float* bias = (const float*)d_in[2];
    const float* Dw   = (const float*)d_in[3];
    const float* Db   = (const float*)d_in[4];
    float* out = (float*)d_out;
    rnn_sample_kernel<<<NBLOCKS, THREADS>>>(Wx, Wh, bias, Dw, Db, out);
}